// round 6
// baseline (speedup 1.0000x reference)
#include <cuda_runtime.h>

#define RFN 512
#define TN  32
#define THN 16               // t-rows per CTA (t-split factor 2)
#define KN  32
#define LN  2048
#define BK  32
#define NTILE (LN / BK)      // 64
#define STAGES 4
#define THREADS 32

__device__ float g_thr[RFN * TN * KN];   // thresholded potentials scratch (2 MB)

// Packed double fp32 FMA (Blackwell FFMA2) — only reachable via PTX fma.rn.f32x2.
__device__ __forceinline__ unsigned long long ffma2(unsigned long long a,
                                                    unsigned long long b,
                                                    unsigned long long c) {
    unsigned long long d;
    asm volatile("fma.rn.f32x2 %0, %1, %2, %3;" : "=l"(d) : "l"(a), "l"(b), "l"(c));
    return d;
}

__device__ __forceinline__ void cp_async16(unsigned dst, const float* src) {
    asm volatile("cp.async.cg.shared.global [%0], [%1], 16;" :: "r"(dst), "l"(src) : "memory");
}

// 16B-chunk XOR swizzle: chunk (row, c4) lives at column (c4 ^ (row & 7)).
#define SWZ(row, c4) ((c4) ^ ((row) & 7))

// ---------------------------------------------------------------------------
// Kernel 1: per-(branch, t-half) GEMM -> thresholded potentials to scratch.
// grid = 1024 (branch = bid>>1, t-half = bid&1), block = 32 (one warp).
// Each output's reduction chain is bitwise identical to previous rounds.
// ---------------------------------------------------------------------------
__global__ __launch_bounds__(THREADS)
void spyke_gemm(const float* __restrict__ rec,   // (T=32, C=1, RF=512, L=2048)
                const float* __restrict__ Wt)    // (RF=512, K=32, C=1, L=2048)
{
    __shared__ __align__(16) float As[STAGES][THN][BK];   // swizzled chunks
    __shared__ __align__(16) float Bs[STAGES][KN][BK];

    const int lane = threadIdx.x;      // 0..31
    const int rg = lane >> 3;          // 0..3 -> t rows {rg, rg+4, rg+8, rg+12}
    const int cg = lane & 7;           // 0..7 -> k cols {cg, cg+8, cg+16, cg+24}
    const int r  = blockIdx.x >> 1;
    const int tb = (blockIdx.x & 1) * THN;   // global t base for this CTA

    // A row (local row 0..15) -> global elem rec[(tb+row)*512*2048 + r*2048 + l]
    const float* Abase = rec + ((size_t)tb * RFN + r) * LN;
    const float* Bbase = Wt  + (size_t)r * KN * LN;

    const unsigned sA = (unsigned)__cvta_generic_to_shared(&As[0][0][0]);
    const unsigned sB = (unsigned)__cvta_generic_to_shared(&Bs[0][0][0]);
    const unsigned STGA = THN * BK * 4;   // 2048 B
    const unsigned STGB = KN * BK * 4;    // 4096 B

    // acc[j][c]: output (t_local = rg+4j, k = cg+8c); (even-l, odd-l) f32x2
    unsigned long long acc[4][4];
#pragma unroll
    for (int j = 0; j < 4; j++)
#pragma unroll
        for (int c = 0; c < 4; c++) acc[j][c] = 0ull;

    // ---- prologue: prefetch tiles 0..STAGES-2 ----
#pragma unroll
    for (int s = 0; s < STAGES - 1; s++) {
        const int l0 = s * BK;
#pragma unroll
        for (int i = 0; i < 4; i++) {           // A: 128 chunks / 32 lanes
            int idx = i * 32 + lane;
            int row = idx >> 3, c4 = idx & 7;
            unsigned soff = (unsigned)s * STGA + (unsigned)((row * BK + SWZ(row, c4) * 4) * 4);
            cp_async16(sA + soff, Abase + (size_t)row * (RFN * LN) + l0 + c4 * 4);
        }
#pragma unroll
        for (int i = 0; i < 8; i++) {           // B: 256 chunks / 32 lanes
            int idx = i * 32 + lane;
            int row = idx >> 3, c4 = idx & 7;
            unsigned soff = (unsigned)s * STGB + (unsigned)((row * BK + SWZ(row, c4) * 4) * 4);
            cp_async16(sB + soff, Bbase + (size_t)row * LN + l0 + c4 * 4);
        }
        asm volatile("cp.async.commit_group;" ::: "memory");
    }

    for (int ti = 0; ti < NTILE; ti++) {
        asm volatile("cp.async.wait_group %0;" :: "n"(STAGES - 2) : "memory");
        __syncwarp();   // warp-private pipeline

        if (ti + STAGES - 1 < NTILE) {
            const int tn = ti + STAGES - 1;
            const int st = tn & (STAGES - 1);
            const int l0 = tn * BK;
#pragma unroll
            for (int i = 0; i < 4; i++) {
                int idx = i * 32 + lane;
                int row = idx >> 3, c4 = idx & 7;
                unsigned soff = (unsigned)st * STGA + (unsigned)((row * BK + SWZ(row, c4) * 4) * 4);
                cp_async16(sA + soff, Abase + (size_t)row * (RFN * LN) + l0 + c4 * 4);
            }
#pragma unroll
            for (int i = 0; i < 8; i++) {
                int idx = i * 32 + lane;
                int row = idx >> 3, c4 = idx & 7;
                unsigned soff = (unsigned)st * STGB + (unsigned)((row * BK + SWZ(row, c4) * 4) * 4);
                cp_async16(sB + soff, Bbase + (size_t)row * LN + l0 + c4 * 4);
            }
        }
        asm volatile("cp.async.commit_group;" ::: "memory");

        // ---- compute tile ti ----
        const int buf = ti & (STAGES - 1);
#pragma unroll
        for (int lc4 = 0; lc4 < BK / 4; lc4++) {
            ulonglong2 av[4], bv[4];
#pragma unroll
            for (int j = 0; j < 4; j++) {
                const int row = rg + 4 * j;               // rows distinct mod 8 across warp
                av[j] = *(const ulonglong2*)&As[buf][row][(lc4 ^ (row & 7)) * 4];
            }
#pragma unroll
            for (int c = 0; c < 4; c++) {
                const int row = cg + 8 * c;               // row&7 == cg
                bv[c] = *(const ulonglong2*)&Bs[buf][row][(lc4 ^ cg) * 4];
            }
#pragma unroll
            for (int j = 0; j < 4; j++)
#pragma unroll
                for (int c = 0; c < 4; c++) {
                    acc[j][c] = ffma2(av[j].x, bv[c].x, acc[j][c]);
                    acc[j][c] = ffma2(av[j].y, bv[c].y, acc[j][c]);
                }
        }
    }

    // ---- threshold and write to scratch: g_thr[r][t][k] ----
#pragma unroll
    for (int j = 0; j < 4; j++)
#pragma unroll
        for (int c = 0; c < 4; c++) {
            unsigned long long a = acc[j][c];
            float lo = __uint_as_float((unsigned)(a & 0xffffffffull));
            float hi = __uint_as_float((unsigned)(a >> 32));
            float pot = lo + hi;
            float tv  = (pot > 20.0f) ? pot : 0.0f;
            int t = tb + rg + 4 * j;
            int k = cg + 8 * c;
            g_thr[((size_t)r * TN + t) * KN + k] = tv;
        }
}

// ---------------------------------------------------------------------------
// Kernel 2: kWTA per branch + output write. grid = 512, block = 32 (lane = k).
// ---------------------------------------------------------------------------
__global__ __launch_bounds__(THREADS)
void spyke_kwta(float* __restrict__ out)         // (T, 1, K, RF)
{
    const int lane = threadIdx.x;   // feature k
    const int r = blockIdx.x;
    const float* thp = &g_thr[(size_t)r * TN * KN];

    float th_t[TN];
    int cnt = 0;
#pragma unroll
    for (int t = 0; t < TN; t++) {
        th_t[t] = thp[t * KN + lane];
        cnt += (th_t[t] > 0.0f) ? 1 : 0;
    }
    int first = 32 - cnt;
    if (first > 31) first = 31;                  // cnt==0 -> 31 ; cnt>=1 -> 0..31
    float vals = thp[first * KN + lane];
    float vk = (cnt > 0) ? vals : 0.0f;
    float vmax = vk;
#pragma unroll
    for (int o = 16; o > 0; o >>= 1) {
        float ov = __shfl_xor_sync(0xffffffffu, vmax, o);
        vmax = (ov > vmax) ? ov : vmax;
    }
    const float v = vmax * 32.0f;
    const float total = (float)cnt * (vals + v);

    float cur = total;
    bool win = false;
#pragma unroll
    for (int it = 0; it < 4; it++) {
        float bvv = cur;
        int bi = lane;
#pragma unroll
        for (int o = 16; o > 0; o >>= 1) {
            float ov = __shfl_xor_sync(0xffffffffu, bvv, o);
            int   oi = __shfl_xor_sync(0xffffffffu, bi, o);
            if (ov > bvv || (ov == bvv && oi < bi)) { bvv = ov; bi = oi; }
        }
        if (lane == bi) {
            if (cur > 0.0f) win = true;          // valid = top_val != 0
            cur = -1.0f;                         // exclude from later rounds
        }
    }

    // out[t,0,k,r] = (thr>0 && k is winner) ? 1 : 0
#pragma unroll
    for (int t = 0; t < TN; t++) {
        out[(size_t)t * (KN * RFN) + (size_t)lane * RFN + r] =
            (win && th_t[t] > 0.0f) ? 1.0f : 0.0f;
    }
}

extern "C" void kernel_launch(void* const* d_in, const int* in_sizes, int n_in,
                              void* d_out, int out_size) {
    const float* rec = (const float*)d_in[0];   // rec_field (32,1,512,2048)
    const float* Wt  = (const float*)d_in[1];   // W (512,32,1,2048)
    // d_in[2] = reward — unused by the reference output
    float* out = (float*)d_out;                 // (32,1,32,512)
    spyke_gemm<<<RFN * 2, THREADS>>>(rec, Wt);
    spyke_kwta<<<RFN, THREADS>>>(out);
}